// round 8
// baseline (speedup 1.0000x reference)
#include <cuda_runtime.h>
#include <cuda_bf16.h>
#include <cstdint>

#define B_   8
#define T_   2048
#define HID_ 1024
#define HS_  64
#define NEG_BIG (-3.0e38f)

// scratch: q, k [B][T][HS];  v TRANSPOSED [B][HS][T]; all tf32-rounded fp32
__device__ float g_q[B_ * T_ * HS_];
__device__ float g_k[B_ * T_ * HS_];
__device__ float g_v[B_ * T_ * HS_];
__device__ int   g_ctr;              // persistent work queue counter

// ===========================================================================
// helpers (baseline PTX ISA, compiles for sm_100)
// ===========================================================================
__device__ __forceinline__ uint32_t smem_u32(const void* p) {
    uint32_t a;
    asm("{ .reg .u64 t; cvta.to.shared.u64 t, %1; cvt.u32.u64 %0, t; }" : "=r"(a) : "l"(p));
    return a;
}

#define LDSM_X4(r, addr) \
    asm volatile("ldmatrix.sync.aligned.m8n8.x4.shared.b16 {%0,%1,%2,%3}, [%4];" \
        : "=r"((r)[0]), "=r"((r)[1]), "=r"((r)[2]), "=r"((r)[3]) : "r"(addr))

#define LDSM_X4_T(r, addr) \
    asm volatile("ldmatrix.sync.aligned.m8n8.x4.trans.shared.b16 {%0,%1,%2,%3}, [%4];" \
        : "=r"((r)[0]), "=r"((r)[1]), "=r"((r)[2]), "=r"((r)[3]) : "r"(addr))

#define MMA16816(d, a, b0, b1) \
    asm volatile("mma.sync.aligned.m16n8k16.row.col.f32.bf16.bf16.f32 " \
        "{%0,%1,%2,%3},{%4,%5,%6,%7},{%8,%9},{%0,%1,%2,%3};" \
        : "+f"((d)[0]), "+f"((d)[1]), "+f"((d)[2]), "+f"((d)[3]) \
        : "r"((a)[0]), "r"((a)[1]), "r"((a)[2]), "r"((a)[3]), "r"(b0), "r"(b1))

#define MMATF32(d, a, b0, b1) \
    asm volatile("mma.sync.aligned.m16n8k8.row.col.f32.tf32.tf32.f32 " \
        "{%0,%1,%2,%3},{%4,%5,%6,%7},{%8,%9},{%0,%1,%2,%3};" \
        : "+f"((d)[0]), "+f"((d)[1]), "+f"((d)[2]), "+f"((d)[3]) \
        : "r"((a)[0]), "r"((a)[1]), "r"((a)[2]), "r"((a)[3]), "r"(b0), "r"(b1))

__device__ __forceinline__ float to_tf32(float x) {
    uint32_t u;
    asm("cvt.rna.tf32.f32 %0, %1;" : "=r"(u) : "f"(x));
    return __uint_as_float(u);
}

#define CPA(dst, src) asm volatile("cp.async.ca.shared.global [%0], [%1], 16;" \
    :: "r"(dst), "l"(__cvta_generic_to_global(src)) : "memory")
#define CPC()  asm volatile("cp.async.commit_group;" ::: "memory")
#define CPW(n) asm volatile("cp.async.wait_group %0;" :: "n"(n) : "memory")

__device__ __forceinline__ void split4(float4 v, uint2& h, uint2& l) {
    __nv_bfloat16 h0 = __float2bfloat16(v.x);
    __nv_bfloat16 h1 = __float2bfloat16(v.y);
    __nv_bfloat16 h2 = __float2bfloat16(v.z);
    __nv_bfloat16 h3 = __float2bfloat16(v.w);
    __nv_bfloat16 l0 = __float2bfloat16(v.x - __bfloat162float(h0));
    __nv_bfloat16 l1 = __float2bfloat16(v.y - __bfloat162float(h1));
    __nv_bfloat16 l2 = __float2bfloat16(v.z - __bfloat162float(h2));
    __nv_bfloat16 l3 = __float2bfloat16(v.w - __bfloat162float(h3));
    h.x = ((uint32_t)__bfloat16_as_ushort(h1) << 16) | __bfloat16_as_ushort(h0);
    h.y = ((uint32_t)__bfloat16_as_ushort(h3) << 16) | __bfloat16_as_ushort(h2);
    l.x = ((uint32_t)__bfloat16_as_ushort(l1) << 16) | __bfloat16_as_ushort(l0);
    l.y = ((uint32_t)__bfloat16_as_ushort(l3) << 16) | __bfloat16_as_ushort(l2);
}

// ===========================================================================
// Kernel 1: QKV projection via mma.sync bf16, 2-term split (near-fp32).
// EXACT R5 structure (verified passing); min-blocks 2 for co-residency.
// ===========================================================================
#define AHI_OFF 0
#define ALO_OFF 8192
#define BHI_OFF 16384
#define BLO_OFF 40960
#define QKV_SMEM 65536

__global__ __launch_bounds__(256, 2)
void qkv_mma_kernel(const float* __restrict__ x,
                    const float* __restrict__ Wq,
                    const float* __restrict__ Wk,
                    const float* __restrict__ Wv)
{
    extern __shared__ char sm[];
    const uint32_t sb = smem_u32(sm);

    if (blockIdx.x == 0 && threadIdx.x == 0) g_ctr = 0;   // reset attn queue

    const int tx   = threadIdx.x;
    const int wid  = tx >> 5;
    const int lane = tx & 31;
    const int row0 = blockIdx.x * 64;

    const int warp_m = wid & 3;
    const int warp_n = wid >> 2;
    const int wr0 = warp_m * 16;
    const int wn0 = warp_n * 96;

    const float* __restrict__ Wm[3] = { Wq, Wk, Wv };

    const int a_r    = wr0 + (lane & 7) + ((lane >> 3) & 1) * 8;
    const int a_koff = (lane >> 4) << 3;
    const int a_r128 = a_r * 128;
    const int a_xr   = (a_r & 7) << 4;

    const int b_k    = (lane & 7) + ((lane >> 3) & 1) * 8;
    const int b_n0   = wn0 + ((lane >> 4) << 3);
    const int b_xr   = (b_k & 7) << 4;

    float acc[12][4] = {};

    for (int kt = 0; kt < HID_ / 64; kt++) {
        const int k0 = kt * 64;

        #pragma unroll
        for (int p = 0; p < 4; p++) {
            int idx = tx + 256 * p;
            int r = idx >> 4, c4 = (idx & 15) << 2;
            float4 v = *(const float4*)(x + (size_t)(row0 + r) * HID_ + k0 + c4);
            uint2 h, l; split4(v, h, l);
            uint32_t byte = (uint32_t)(r * 128 + c4 * 2) ^ ((r & 7) << 4);
            *(uint2*)(sm + AHI_OFF + byte) = h;
            *(uint2*)(sm + ALO_OFF + byte) = l;
        }
        #pragma unroll
        for (int p = 0; p < 12; p++) {
            int idx = tx + 256 * p;
            int mat = idx >> 10, rem = idx & 1023;
            int k = rem >> 4, n4 = (rem & 15) << 2;
            float4 v = *(const float4*)(Wm[mat] + (size_t)(k0 + k) * HS_ + n4);
            uint2 h, l; split4(v, h, l);
            uint32_t byte = (uint32_t)(k * 384 + mat * 128 + n4 * 2) ^ ((k & 7) << 4);
            *(uint2*)(sm + BHI_OFF + byte) = h;
            *(uint2*)(sm + BLO_OFF + byte) = l;
        }
        __syncthreads();

        #pragma unroll
        for (int ks = 0; ks < 4; ks++) {
            const int kk = ks * 16 + a_koff;
            const uint32_t aoff = (uint32_t)(a_r128 + kk * 2) ^ a_xr;
            uint32_t ah[4], al[4];
            LDSM_X4(ah, sb + AHI_OFF + aoff);
            LDSM_X4(al, sb + ALO_OFF + aoff);

            const int bk = ks * 16 + b_k;
            #pragma unroll
            for (int pr = 0; pr < 6; pr++) {
                const int n = b_n0 + pr * 16;
                const uint32_t boff = (uint32_t)(bk * 384 + n * 2) ^ b_xr;
                uint32_t bh[4], bl[4];
                LDSM_X4_T(bh, sb + BHI_OFF + boff);
                LDSM_X4_T(bl, sb + BLO_OFF + boff);
                MMA16816(acc[2 * pr],     ah, bh[0], bh[1]);
                MMA16816(acc[2 * pr],     ah, bl[0], bl[1]);
                MMA16816(acc[2 * pr],     al, bh[0], bh[1]);
                MMA16816(acc[2 * pr + 1], ah, bh[2], bh[3]);
                MMA16816(acc[2 * pr + 1], ah, bl[2], bl[3]);
                MMA16816(acc[2 * pr + 1], al, bh[2], bh[3]);
            }
        }
        __syncthreads();
    }

    // epilogue: tf32-round; q scaled; v transposed [B][HS][T]
    const int r_lo = row0 + wr0 + (lane >> 2);
    #pragma unroll
    for (int nt = 0; nt < 12; nt++) {
        int nglob = wn0 + nt * 8 + (lane & 3) * 2;
        int mat = nglob >> 6;
        int col = nglob & 63;
        if (mat < 2) {
            float sc = (mat == 0) ? 0.03125f : 1.0f;
            float* dst = (mat == 0 ? g_q : g_k);
            float2 v0 = { to_tf32(acc[nt][0] * sc), to_tf32(acc[nt][1] * sc) };
            float2 v1 = { to_tf32(acc[nt][2] * sc), to_tf32(acc[nt][3] * sc) };
            *(float2*)(dst + (size_t)r_lo * HS_ + col)       = v0;
            *(float2*)(dst + (size_t)(r_lo + 8) * HS_ + col) = v1;
        } else {
            int bb = r_lo >> 11, tl = r_lo & 2047;
            float* dst = g_v + (size_t)bb * HS_ * T_;
            dst[(size_t)col * T_ + tl]           = to_tf32(acc[nt][0]);
            dst[(size_t)(col + 1) * T_ + tl]     = to_tf32(acc[nt][1]);
            dst[(size_t)col * T_ + tl + 8]       = to_tf32(acc[nt][2]);
            dst[(size_t)(col + 1) * T_ + tl + 8] = to_tf32(acc[nt][3]);
        }
    }
}

// ===========================================================================
// Kernel 2: causal attention on tf32 mma.sync, 2 CTAs/SM persistent, LPT
// queue. RACE FIX vs R5/R7: the cp.async prefetch for tile j+1 is issued
// AFTER the top-of-iteration __syncthreads(), so no thread can overwrite a
// K/V buffer until every thread has finished the PV reads of the iteration
// that last used it. Wait is CPW(0); the prefetch still overlaps the whole
// QK + softmax + PV of the current tile.
// ===========================================================================
#define PITCH  68
#define TILE_B (64 * PITCH * 4)         // 17408
#define OFF_K0 0
#define OFF_K1 TILE_B
#define OFF_V0 (2 * TILE_B)
#define OFF_V1 (3 * TILE_B)
#define OFF_P  (4 * TILE_B)
#define OFF_X  (5 * TILE_B)             // 128 floats of l-exchange
#define OFF_TS (OFF_X + 512)
#define ATTN_SMEM (OFF_TS + 16)
#define NTASKS 256

__global__ __launch_bounds__(256, 2)
void attn_tc_kernel(float* __restrict__ out)
{
    extern __shared__ char sm[];
    const uint32_t sb = smem_u32(sm);
    float* xb = (float*)(sm + OFF_X);
    int* tslot = (int*)(sm + OFF_TS);

    const int tx = threadIdx.x, wid = tx >> 5, lane = tx & 31;
    const int strip = wid >> 1, wn = wid & 1;
    const int gid = lane >> 2, tig = lane & 3;

    for (;;) {
        __syncthreads();                 // prior task fully done (incl. PV reads)
        if (tx == 0) *tslot = atomicAdd(&g_ctr, 1);
        __syncthreads();
        const int t = *tslot;
        if (t >= NTASKS) break;

        const int it = 31 - (t >> 3);          // LPT: big tasks first
        const int b  = t & 7;
        const int i0 = it * 64;

        const float* __restrict__ qb  = g_q + (size_t)b * T_ * HS_;
        const float* __restrict__ kb  = g_k + (size_t)b * T_ * HS_;
        const float* __restrict__ vtb = g_v + (size_t)b * HS_ * T_;

        // prefetch tile 0 (safe: barrier above guarantees prior task's reads done)
        #pragma unroll
        for (int p = 0; p < 4; p++) {
            int idx = tx + 256 * p;
            int r = idx >> 4, c = idx & 15;
            CPA(sb + OFF_K0 + r * 272 + c * 16, kb + (size_t)r * HS_ + c * 4);
            CPA(sb + OFF_V0 + r * 272 + c * 16, vtb + (size_t)r * T_ + c * 4);
        }
        CPC();

        uint32_t qf[8][4];
        {
            const int r = i0 + strip * 16 + gid;
            #pragma unroll
            for (int kc = 0; kc < 8; kc++) {
                qf[kc][0] = __float_as_uint(qb[(size_t)r * HS_ + kc * 8 + tig]);
                qf[kc][1] = __float_as_uint(qb[(size_t)(r + 8) * HS_ + kc * 8 + tig]);
                qf[kc][2] = __float_as_uint(qb[(size_t)r * HS_ + kc * 8 + tig + 4]);
                qf[kc][3] = __float_as_uint(qb[(size_t)(r + 8) * HS_ + kc * 8 + tig + 4]);
            }
        }

        float oacc[4][4] = {};
        float l0 = 0.f, l1 = 0.f;

        for (int j = 0; j <= it; j++) {
            CPW(0);            // KV(j) landed
            __syncthreads();   // ...and ALL threads are done with PV reads of j-1

            // now (and only now) safe to start overwriting buffer (j+1)&1
            if (j < it) {
                const uint32_t ko = ((j + 1) & 1) ? OFF_K1 : OFF_K0;
                const uint32_t vo = ((j + 1) & 1) ? OFF_V1 : OFF_V0;
                const int j1 = (j + 1) * 64;
                #pragma unroll
                for (int p = 0; p < 4; p++) {
                    int idx = tx + 256 * p;
                    int r = idx >> 4, c = idx & 15;
                    CPA(sb + ko + r * 272 + c * 16, kb + (size_t)(j1 + r) * HS_ + c * 4);
                    CPA(sb + vo + r * 272 + c * 16, vtb + (size_t)r * T_ + j1 + c * 4);
                }
                CPC();
            }

            const uint32_t* Kb = (const uint32_t*)(sm + ((j & 1) ? OFF_K1 : OFF_K0));
            const uint32_t* Vb = (const uint32_t*)(sm + ((j & 1) ? OFF_V1 : OFF_V0));

            float s[4][4] = {};
            #pragma unroll
            for (int kc = 0; kc < 8; kc++) {
                #pragma unroll
                for (int nf = 0; nf < 4; nf++) {
                    const uint32_t* kp = Kb + (wn * 32 + nf * 8 + gid) * PITCH + kc * 8 + tig;
                    MMATF32(s[nf], qf[kc], kp[0], kp[4]);
                }
            }

            uint32_t* Pp = (uint32_t*)(sm + OFF_P);
            #pragma unroll
            for (int nf = 0; nf < 4; nf++) {
                if (j == it) {
                    const int kk = wn * 32 + nf * 8 + tig * 2;
                    const int rr = strip * 16 + gid;
                    if (kk     > rr)     s[nf][0] = NEG_BIG;
                    if (kk + 1 > rr)     s[nf][1] = NEG_BIG;
                    if (kk     > rr + 8) s[nf][2] = NEG_BIG;
                    if (kk + 1 > rr + 8) s[nf][3] = NEG_BIG;
                }
                float p0 = __expf(s[nf][0]);
                float p1 = __expf(s[nf][1]);
                float p2 = __expf(s[nf][2]);
                float p3 = __expf(s[nf][3]);
                l0 += p0 + p1;
                l1 += p2 + p3;
                uint2 w0, w1;
                asm("cvt.rna.tf32.f32 %0, %1;" : "=r"(w0.x) : "f"(p0));
                asm("cvt.rna.tf32.f32 %0, %1;" : "=r"(w0.y) : "f"(p1));
                asm("cvt.rna.tf32.f32 %0, %1;" : "=r"(w1.x) : "f"(p2));
                asm("cvt.rna.tf32.f32 %0, %1;" : "=r"(w1.y) : "f"(p3));
                const int col = wn * 32 + nf * 8 + tig * 2;
                *(uint2*)(Pp + (strip * 16 + gid) * PITCH + col)     = w0;
                *(uint2*)(Pp + (strip * 16 + gid + 8) * PITCH + col) = w1;
            }
            __syncthreads();   // P visible to partner warps

            #pragma unroll
            for (int kc = 0; kc < 8; kc++) {
                uint32_t pa[4];
                const uint32_t* pp = Pp + (strip * 16 + gid) * PITCH + kc * 8 + tig;
                pa[0] = pp[0];
                pa[1] = pp[8 * PITCH];
                pa[2] = pp[4];
                pa[3] = pp[8 * PITCH + 4];
                #pragma unroll
                for (int nh = 0; nh < 4; nh++) {
                    const uint32_t* vp = Vb + (wn * 32 + nh * 8 + gid) * PITCH + kc * 8 + tig;
                    MMATF32(oacc[nh], pa, vp[0], vp[4]);
                }
            }
            // PV reads of buffer (j&1) protected by the barrier at top of j+1
        }

        l0 += __shfl_xor_sync(0xffffffffu, l0, 1);
        l0 += __shfl_xor_sync(0xffffffffu, l0, 2);
        l1 += __shfl_xor_sync(0xffffffffu, l1, 1);
        l1 += __shfl_xor_sync(0xffffffffu, l1, 2);
        if (tig == 0) {
            xb[(strip * 2 + wn) * 16 + gid]     = l0;
            xb[(strip * 2 + wn) * 16 + gid + 8] = l1;
        }
        __syncthreads();
        const float inv0 = 1.f / (l0 + xb[(strip * 2 + (wn ^ 1)) * 16 + gid]);
        const float inv1 = 1.f / (l1 + xb[(strip * 2 + (wn ^ 1)) * 16 + gid + 8]);

        float* ob = out + (size_t)b * T_ * HS_;
        const int r = i0 + strip * 16 + gid;
        #pragma unroll
        for (int nh = 0; nh < 4; nh++) {
            const int h = wn * 32 + nh * 8 + tig * 2;
            float2 v0 = { oacc[nh][0] * inv0, oacc[nh][1] * inv0 };
            float2 v1 = { oacc[nh][2] * inv1, oacc[nh][3] * inv1 };
            *(float2*)(ob + (size_t)r * HS_ + h)       = v0;
            *(float2*)(ob + (size_t)(r + 8) * HS_ + h) = v1;
        }
    }
}

// ===========================================================================
extern "C" void kernel_launch(void* const* d_in, const int* in_sizes, int n_in,
                              void* d_out, int out_size)
{
    const float* x  = (const float*)d_in[0];
    const float* Wq = (const float*)d_in[1];
    const float* Wk = (const float*)d_in[2];
    const float* Wv = (const float*)d_in[3];
    float* out = (float*)d_out;

    static bool configured = false;
    if (!configured) {
        cudaFuncSetAttribute(qkv_mma_kernel,
                             cudaFuncAttributeMaxDynamicSharedMemorySize, QKV_SMEM);
        cudaFuncSetAttribute(attn_tc_kernel,
                             cudaFuncAttributeMaxDynamicSharedMemorySize, ATTN_SMEM);
        configured = true;
    }

    qkv_mma_kernel<<<256, 256, QKV_SMEM>>>(x, Wq, Wk, Wv);
    attn_tc_kernel<<<296, 256, ATTN_SMEM>>>(out);
}

// round 10
// speedup vs baseline: 1.3387x; 1.3387x over previous
#include <cuda_runtime.h>
#include <cuda_bf16.h>
#include <cstdint>

#define B_   8
#define T_   2048
#define HID_ 1024
#define HS_  64
#define NEG_BIG (-3.0e38f)

// scratch: q, k [B][T][HS];  v TRANSPOSED [B][HS][T]; all tf32-rounded fp32
__device__ float g_q[B_ * T_ * HS_];
__device__ float g_k[B_ * T_ * HS_];
__device__ float g_v[B_ * T_ * HS_];
__device__ int   g_ctr;              // persistent work queue counter

// pre-split W (hi/lo bf16), stored as the exact swizzled smem image:
// [16 ktiles][24576 bytes]  (64 k-rows x 384 bytes, 16B-XOR swizzled)
__device__ __align__(16) uint8_t g_wbhi[16 * 24576];
__device__ __align__(16) uint8_t g_wblo[16 * 24576];

// ===========================================================================
// helpers (baseline PTX ISA, compiles for sm_100)
// ===========================================================================
__device__ __forceinline__ uint32_t smem_u32(const void* p) {
    uint32_t a;
    asm("{ .reg .u64 t; cvta.to.shared.u64 t, %1; cvt.u32.u64 %0, t; }" : "=r"(a) : "l"(p));
    return a;
}

#define LDSM_X4(r, addr) \
    asm volatile("ldmatrix.sync.aligned.m8n8.x4.shared.b16 {%0,%1,%2,%3}, [%4];" \
        : "=r"((r)[0]), "=r"((r)[1]), "=r"((r)[2]), "=r"((r)[3]) : "r"(addr))

#define LDSM_X4_T(r, addr) \
    asm volatile("ldmatrix.sync.aligned.m8n8.x4.trans.shared.b16 {%0,%1,%2,%3}, [%4];" \
        : "=r"((r)[0]), "=r"((r)[1]), "=r"((r)[2]), "=r"((r)[3]) : "r"(addr))

#define MMA16816(d, a, b0, b1) \
    asm volatile("mma.sync.aligned.m16n8k16.row.col.f32.bf16.bf16.f32 " \
        "{%0,%1,%2,%3},{%4,%5,%6,%7},{%8,%9},{%0,%1,%2,%3};" \
        : "+f"((d)[0]), "+f"((d)[1]), "+f"((d)[2]), "+f"((d)[3]) \
        : "r"((a)[0]), "r"((a)[1]), "r"((a)[2]), "r"((a)[3]), "r"(b0), "r"(b1))

#define MMATF32(d, a, b0, b1) \
    asm volatile("mma.sync.aligned.m16n8k8.row.col.f32.tf32.tf32.f32 " \
        "{%0,%1,%2,%3},{%4,%5,%6,%7},{%8,%9},{%0,%1,%2,%3};" \
        : "+f"((d)[0]), "+f"((d)[1]), "+f"((d)[2]), "+f"((d)[3]) \
        : "r"((a)[0]), "r"((a)[1]), "r"((a)[2]), "r"((a)[3]), "r"(b0), "r"(b1))

__device__ __forceinline__ float to_tf32(float x) {
    uint32_t u;
    asm("cvt.rna.tf32.f32 %0, %1;" : "=r"(u) : "f"(x));
    return __uint_as_float(u);
}

#define CPA(dst, src) asm volatile("cp.async.ca.shared.global [%0], [%1], 16;" \
    :: "r"(dst), "l"(__cvta_generic_to_global(src)) : "memory")
#define CPC()  asm volatile("cp.async.commit_group;" ::: "memory")
#define CPW(n) asm volatile("cp.async.wait_group %0;" :: "n"(n) : "memory")

__device__ __forceinline__ void split4(float4 v, uint2& h, uint2& l) {
    __nv_bfloat16 h0 = __float2bfloat16(v.x);
    __nv_bfloat16 h1 = __float2bfloat16(v.y);
    __nv_bfloat16 h2 = __float2bfloat16(v.z);
    __nv_bfloat16 h3 = __float2bfloat16(v.w);
    __nv_bfloat16 l0 = __float2bfloat16(v.x - __bfloat162float(h0));
    __nv_bfloat16 l1 = __float2bfloat16(v.y - __bfloat162float(h1));
    __nv_bfloat16 l2 = __float2bfloat16(v.z - __bfloat162float(h2));
    __nv_bfloat16 l3 = __float2bfloat16(v.w - __bfloat162float(h3));
    h.x = ((uint32_t)__bfloat16_as_ushort(h1) << 16) | __bfloat16_as_ushort(h0);
    h.y = ((uint32_t)__bfloat16_as_ushort(h3) << 16) | __bfloat16_as_ushort(h2);
    l.x = ((uint32_t)__bfloat16_as_ushort(l1) << 16) | __bfloat16_as_ushort(l0);
    l.y = ((uint32_t)__bfloat16_as_ushort(l3) << 16) | __bfloat16_as_ushort(l2);
}

// ===========================================================================
// Kernel 0: one-shot W split into the swizzled global image.
// ===========================================================================
__global__ __launch_bounds__(256)
void wsplit_kernel(const float* __restrict__ Wq,
                   const float* __restrict__ Wk,
                   const float* __restrict__ Wv)
{
    int idx = blockIdx.x * 256 + threadIdx.x;     // 0..49151 float4s
    int mat = idx >> 14;
    int rem = idx & 16383;
    int k   = rem >> 4;
    int n4  = (rem & 15) << 2;
    const float* W = (mat == 0) ? Wq : (mat == 1) ? Wk : Wv;
    float4 v = *(const float4*)(W + (size_t)k * HS_ + n4);
    uint2 h, l; split4(v, h, l);
    uint32_t byte = (uint32_t)((k >> 6) * 24576 + (k & 63) * 384
                  + ((mat * 128 + n4 * 2) ^ ((k & 7) << 4)));
    *(uint2*)(g_wbhi + byte) = h;
    *(uint2*)(g_wblo + byte) = l;
}

// ===========================================================================
// Kernel 1: QKV projection via mma.sync bf16, 2-term split (near-fp32).
// Double-buffered: B tiles raw cp.async from pre-split image, x tiles
// register-prefetched and split on the fly. One barrier per k-tile.
// ===========================================================================
#define AHI_OFF 0
#define ALO_OFF 8192
#define BHI_OFF 16384
#define BLO_OFF 40960
#define BUFSZ   65536
#define QKV_SMEM (2 * BUFSZ)

__global__ __launch_bounds__(256, 1)
void qkv_mma_kernel(const float* __restrict__ x)
{
    extern __shared__ char sm[];
    const uint32_t sb = smem_u32(sm);

    if (blockIdx.x == 0 && threadIdx.x == 0) g_ctr = 0;   // reset attn queue

    const int tx   = threadIdx.x;
    const int wid  = tx >> 5;
    const int lane = tx & 31;
    const int row0 = blockIdx.x * 64;

    const int warp_m = wid & 3;
    const int warp_n = wid >> 2;
    const int wr0 = warp_m * 16;
    const int wn0 = warp_n * 96;

    const int a_r    = wr0 + (lane & 7) + ((lane >> 3) & 1) * 8;
    const int a_koff = (lane >> 4) << 3;
    const int a_r128 = a_r * 128;
    const int a_xr   = (a_r & 7) << 4;

    const int b_k    = (lane & 7) + ((lane >> 3) & 1) * 8;
    const int b_n0   = wn0 + ((lane >> 4) << 3);
    const int b_xr   = (b_k & 7) << 4;

    float acc[12][4] = {};
    float4 px[4];

    // ---- prologue: issue B(0), load + split-store A(0) into buf0
    #pragma unroll
    for (int p = 0; p < 6; p++) {
        int ch = tx + 256 * p;
        CPA(sb + BHI_OFF + ch * 16, g_wbhi + ch * 16);
        CPA(sb + BLO_OFF + ch * 16, g_wblo + ch * 16);
    }
    CPC();
    #pragma unroll
    for (int p = 0; p < 4; p++) {
        int idx = tx + 256 * p;
        px[p] = *(const float4*)(x + (size_t)(row0 + (idx >> 4)) * HID_ + ((idx & 15) << 2));
    }
    #pragma unroll
    for (int p = 0; p < 4; p++) {
        int idx = tx + 256 * p;
        int r = idx >> 4, c4 = (idx & 15) << 2;
        uint2 h, l; split4(px[p], h, l);
        uint32_t byte = (uint32_t)(r * 128 + c4 * 2) ^ ((r & 7) << 4);
        *(uint2*)(sm + AHI_OFF + byte) = h;
        *(uint2*)(sm + ALO_OFF + byte) = l;
    }

    for (int kt = 0; kt < 16; kt++) {
        const uint32_t cur = (kt & 1) * BUFSZ;
        const uint32_t nxt = ((kt + 1) & 1) * BUFSZ;

        CPW(0);            // B(kt) landed (this thread's copies)
        __syncthreads();   // A(kt) stores visible + everyone done with prev buffer

        if (kt < 15) {
            // stream B(kt+1) into the other buffer (overlaps compute below)
            const uint8_t* sh = g_wbhi + (kt + 1) * 24576;
            const uint8_t* sl = g_wblo + (kt + 1) * 24576;
            #pragma unroll
            for (int p = 0; p < 6; p++) {
                int ch = tx + 256 * p;
                CPA(sb + nxt + BHI_OFF + ch * 16, sh + ch * 16);
                CPA(sb + nxt + BLO_OFF + ch * 16, sl + ch * 16);
            }
            CPC();
            // prefetch x(kt+1) into registers
            const int k1 = (kt + 1) * 64;
            #pragma unroll
            for (int p = 0; p < 4; p++) {
                int idx = tx + 256 * p;
                px[p] = *(const float4*)(x + (size_t)(row0 + (idx >> 4)) * HID_ + k1 + ((idx & 15) << 2));
            }
        }

        // ---- compute on current buffer: 4 k-steps of 16
        #pragma unroll
        for (int ks = 0; ks < 4; ks++) {
            const int kk = ks * 16 + a_koff;
            const uint32_t aoff = ((uint32_t)(a_r128 + kk * 2) ^ a_xr) + cur;
            uint32_t ah[4], al[4];
            LDSM_X4(ah, sb + AHI_OFF + aoff);
            LDSM_X4(al, sb + ALO_OFF + aoff);

            const int bk = ks * 16 + b_k;
            #pragma unroll
            for (int pr = 0; pr < 6; pr++) {
                const int n = b_n0 + pr * 16;
                const uint32_t boff = ((uint32_t)(bk * 384 + n * 2) ^ b_xr) + cur;
                uint32_t bh[4], bl[4];
                LDSM_X4_T(bh, sb + BHI_OFF + boff);
                LDSM_X4_T(bl, sb + BLO_OFF + boff);
                MMA16816(acc[2 * pr],     ah, bh[0], bh[1]);
                MMA16816(acc[2 * pr],     ah, bl[0], bl[1]);
                MMA16816(acc[2 * pr],     al, bh[0], bh[1]);
                MMA16816(acc[2 * pr + 1], ah, bh[2], bh[3]);
                MMA16816(acc[2 * pr + 1], ah, bl[2], bl[3]);
                MMA16816(acc[2 * pr + 1], al, bh[2], bh[3]);
            }
        }

        if (kt < 15) {
            // split-store A(kt+1) into the other buffer (readers gated by
            // the kt+1 top barrier; writers here conflict with nothing)
            #pragma unroll
            for (int p = 0; p < 4; p++) {
                int idx = tx + 256 * p;
                int r = idx >> 4, c4 = (idx & 15) << 2;
                uint2 h, l; split4(px[p], h, l);
                uint32_t byte = ((uint32_t)(r * 128 + c4 * 2) ^ ((r & 7) << 4)) + nxt;
                *(uint2*)(sm + AHI_OFF + byte) = h;
                *(uint2*)(sm + ALO_OFF + byte) = l;
            }
        }
    }

    // epilogue: tf32-round; q scaled; v transposed [B][HS][T]
    const int r_lo = row0 + wr0 + (lane >> 2);
    #pragma unroll
    for (int nt = 0; nt < 12; nt++) {
        int nglob = wn0 + nt * 8 + (lane & 3) * 2;
        int mat = nglob >> 6;
        int col = nglob & 63;
        if (mat < 2) {
            float sc = (mat == 0) ? 0.03125f : 1.0f;
            float* dst = (mat == 0 ? g_q : g_k);
            float2 v0 = { to_tf32(acc[nt][0] * sc), to_tf32(acc[nt][1] * sc) };
            float2 v1 = { to_tf32(acc[nt][2] * sc), to_tf32(acc[nt][3] * sc) };
            *(float2*)(dst + (size_t)r_lo * HS_ + col)       = v0;
            *(float2*)(dst + (size_t)(r_lo + 8) * HS_ + col) = v1;
        } else {
            int bb = r_lo >> 11, tl = r_lo & 2047;
            float* dst = g_v + (size_t)bb * HS_ * T_;
            dst[(size_t)col * T_ + tl]           = to_tf32(acc[nt][0]);
            dst[(size_t)(col + 1) * T_ + tl]     = to_tf32(acc[nt][1]);
            dst[(size_t)col * T_ + tl + 8]       = to_tf32(acc[nt][2]);
            dst[(size_t)(col + 1) * T_ + tl + 8] = to_tf32(acc[nt][3]);
        }
    }
}

// ===========================================================================
// Kernel 2: causal attention on tf32 mma.sync. 148 persistent blocks (1/SM,
// the balanced-LPT config from R5) with TRIPLE-buffered K/V: the prefetch of
// tile j+2 is issued after the top-of-iteration barrier (which proves all PV
// reads of buffer (j+2)%3 == (j-1)%3 finished -> race-free), and CPW(1)
// keeps one group in flight -> full overlap like R5, without R5's race.
// ===========================================================================
#define PITCH  68
#define TILE_B (64 * PITCH * 4)         // 17408
#define OFF_KB 0                        // 3 K buffers
#define OFF_VB (3 * TILE_B)             // 3 V buffers
#define OFF_P  (6 * TILE_B)
#define OFF_X  (7 * TILE_B)             // 128 floats of l-exchange
#define OFF_TS (OFF_X + 512)
#define ATTN_SMEM (OFF_TS + 16)         // 122384
#define NTASKS 256

__global__ __launch_bounds__(256, 1)
void attn_tc_kernel(float* __restrict__ out)
{
    extern __shared__ char sm[];
    const uint32_t sb = smem_u32(sm);
    float* xb = (float*)(sm + OFF_X);
    int* tslot = (int*)(sm + OFF_TS);

    const int tx = threadIdx.x, wid = tx >> 5, lane = tx & 31;
    const int strip = wid >> 1, wn = wid & 1;
    const int gid = lane >> 2, tig = lane & 3;

    for (;;) {
        __syncthreads();                 // prior task fully done (incl. PV reads)
        if (tx == 0) *tslot = atomicAdd(&g_ctr, 1);
        __syncthreads();
        const int t = *tslot;
        if (t >= NTASKS) break;

        const int it = 31 - (t >> 3);          // LPT: big tasks first
        const int b  = t & 7;
        const int i0 = it * 64;

        const float* __restrict__ qb  = g_q + (size_t)b * T_ * HS_;
        const float* __restrict__ kb  = g_k + (size_t)b * T_ * HS_;
        const float* __restrict__ vtb = g_v + (size_t)b * HS_ * T_;

        // prologue: prefetch KV(0) and (if present) KV(1) into bufs 0, 1
        #pragma unroll
        for (int pre = 0; pre < 2; pre++) {
            if (pre > it) break;
            const uint32_t ko = OFF_KB + pre * TILE_B;
            const uint32_t vo = OFF_VB + pre * TILE_B;
            const int j0 = pre * 64;
            #pragma unroll
            for (int p = 0; p < 4; p++) {
                int idx = tx + 256 * p;
                int r = idx >> 4, c = idx & 15;
                CPA(sb + ko + r * 272 + c * 16, kb + (size_t)(j0 + r) * HS_ + c * 4);
                CPA(sb + vo + r * 272 + c * 16, vtb + (size_t)r * T_ + j0 + c * 4);
            }
            CPC();
        }

        uint32_t qf[8][4];
        {
            const int r = i0 + strip * 16 + gid;
            #pragma unroll
            for (int kc = 0; kc < 8; kc++) {
                qf[kc][0] = __float_as_uint(qb[(size_t)r * HS_ + kc * 8 + tig]);
                qf[kc][1] = __float_as_uint(qb[(size_t)(r + 8) * HS_ + kc * 8 + tig]);
                qf[kc][2] = __float_as_uint(qb[(size_t)r * HS_ + kc * 8 + tig + 4]);
                qf[kc][3] = __float_as_uint(qb[(size_t)(r + 8) * HS_ + kc * 8 + tig + 4]);
            }
        }

        float oacc[4][4] = {};
        float l0 = 0.f, l1 = 0.f;
        int bi = 0;                      // buffer holding tile j

        for (int j = 0; j <= it; j++) {
            if (j < it) { CPW(1); } else { CPW(0); }   // KV(j) landed
            __syncthreads();   // + all threads done with PV reads of j-1

            if (j + 2 <= it) {
                int pb = bi - 1; if (pb < 0) pb += 3;  // (bi+2)%3, free per barrier
                const uint32_t ko = OFF_KB + pb * TILE_B;
                const uint32_t vo = OFF_VB + pb * TILE_B;
                const int j2 = (j + 2) * 64;
                #pragma unroll
                for (int p = 0; p < 4; p++) {
                    int idx = tx + 256 * p;
                    int r = idx >> 4, c = idx & 15;
                    CPA(sb + ko + r * 272 + c * 16, kb + (size_t)(j2 + r) * HS_ + c * 4);
                    CPA(sb + vo + r * 272 + c * 16, vtb + (size_t)r * T_ + j2 + c * 4);
                }
                CPC();
            }

            const uint32_t* Kb = (const uint32_t*)(sm + OFF_KB + bi * TILE_B);
            const uint32_t* Vb = (const uint32_t*)(sm + OFF_VB + bi * TILE_B);

            float s[4][4] = {};
            #pragma unroll
            for (int kc = 0; kc < 8; kc++) {
                #pragma unroll
                for (int nf = 0; nf < 4; nf++) {
                    const uint32_t* kp = Kb + (wn * 32 + nf * 8 + gid) * PITCH + kc * 8 + tig;
                    MMATF32(s[nf], qf[kc], kp[0], kp[4]);
                }
            }

            uint32_t* Pp = (uint32_t*)(sm + OFF_P);
            #pragma unroll
            for (int nf = 0; nf < 4; nf++) {
                if (j == it) {
                    const int kk = wn * 32 + nf * 8 + tig * 2;
                    const int rr = strip * 16 + gid;
                    if (kk     > rr)     s[nf][0] = NEG_BIG;
                    if (kk + 1 > rr)     s[nf][1] = NEG_BIG;
                    if (kk     > rr + 8) s[nf][2] = NEG_BIG;
                    if (kk + 1 > rr + 8) s[nf][3] = NEG_BIG;
                }
                float p0 = __expf(s[nf][0]);
                float p1 = __expf(s[nf][1]);
                float p2 = __expf(s[nf][2]);
                float p3 = __expf(s[nf][3]);
                l0 += p0 + p1;
                l1 += p2 + p3;
                uint2 w0, w1;
                asm("cvt.rna.tf32.f32 %0, %1;" : "=r"(w0.x) : "f"(p0));
                asm("cvt.rna.tf32.f32 %0, %1;" : "=r"(w0.y) : "f"(p1));
                asm("cvt.rna.tf32.f32 %0, %1;" : "=r"(w1.x) : "f"(p2));
                asm("cvt.rna.tf32.f32 %0, %1;" : "=r"(w1.y) : "f"(p3));
                const int col = wn * 32 + nf * 8 + tig * 2;
                *(uint2*)(Pp + (strip * 16 + gid) * PITCH + col)     = w0;
                *(uint2*)(Pp + (strip * 16 + gid + 8) * PITCH + col) = w1;
            }
            __syncthreads();   // P visible to partner warps

            #pragma unroll
            for (int kc = 0; kc < 8; kc++) {
                uint32_t pa[4];
                const uint32_t* pp = Pp + (strip * 16 + gid) * PITCH + kc * 8 + tig;
                pa[0] = pp[0];
                pa[1] = pp[8 * PITCH];
                pa[2] = pp[4];
                pa[3] = pp[8 * PITCH + 4];
                #pragma unroll
                for (int nh = 0; nh < 4; nh++) {
                    const uint32_t* vp = Vb + (wn * 32 + nh * 8 + gid) * PITCH + kc * 8 + tig;
                    MMATF32(oacc[nh], pa, vp[0], vp[4]);
                }
            }
            bi = (bi + 1 == 3) ? 0 : bi + 1;
            // PV reads of this buffer protected by the barrier at top of j+1
        }

        l0 += __shfl_xor_sync(0xffffffffu, l0, 1);
        l0 += __shfl_xor_sync(0xffffffffu, l0, 2);
        l1 += __shfl_xor_sync(0xffffffffu, l1, 1);
        l1 += __shfl_xor_sync(0xffffffffu, l1, 2);
        if (tig == 0) {
            xb[(strip * 2 + wn) * 16 + gid]     = l0;
            xb[(strip * 2 + wn) * 16 + gid + 8] = l1;
        }
        __syncthreads();
        const float inv0 = 1.f / (l0 + xb[(strip * 2 + (wn ^ 1)) * 16 + gid]);
        const float inv1 = 1.f / (l1 + xb[(strip * 2 + (wn ^ 1)) * 16 + gid + 8]);

        float* ob = out + (size_t)b * T_ * HS_;
        const int r = i0 + strip * 16 + gid;
        #pragma unroll
        for (int nh = 0; nh < 4; nh++) {
            const int h = wn * 32 + nh * 8 + tig * 2;
            float2 v0 = { oacc[nh][0] * inv0, oacc[nh][1] * inv0 };
            float2 v1 = { oacc[nh][2] * inv1, oacc[nh][3] * inv1 };
            *(float2*)(ob + (size_t)r * HS_ + h)       = v0;
            *(float2*)(ob + (size_t)(r + 8) * HS_ + h) = v1;
        }
    }
}

// ===========================================================================
extern "C" void kernel_launch(void* const* d_in, const int* in_sizes, int n_in,
                              void* d_out, int out_size)
{
    const float* x  = (const float*)d_in[0];
    const float* Wq = (const float*)d_in[1];
    const float* Wk = (const float*)d_in[2];
    const float* Wv = (const float*)d_in[3];
    float* out = (float*)d_out;

    static bool configured = false;
    if (!configured) {
        cudaFuncSetAttribute(qkv_mma_kernel,
                             cudaFuncAttributeMaxDynamicSharedMemorySize, QKV_SMEM);
        cudaFuncSetAttribute(attn_tc_kernel,
                             cudaFuncAttributeMaxDynamicSharedMemorySize, ATTN_SMEM);
        configured = true;
    }

    wsplit_kernel<<<192, 256>>>(Wq, Wk, Wv);
    qkv_mma_kernel<<<256, 256, QKV_SMEM>>>(x);
    attn_tc_kernel<<<148, 256, ATTN_SMEM>>>(out);
}

// round 12
// speedup vs baseline: 1.4855x; 1.1096x over previous
#include <cuda_runtime.h>
#include <cuda_bf16.h>
#include <cstdint>

#define B_   8
#define T_   2048
#define HID_ 1024
#define HS_  64
#define NEG_BIG (-3.0e38f)

// scratch: q, k [B][T][HS];  v TRANSPOSED [B][HS][T]; all tf32-rounded fp32
__device__ float g_q[B_ * T_ * HS_];
__device__ float g_k[B_ * T_ * HS_];
__device__ float g_v[B_ * T_ * HS_];
__device__ int   g_ctr;              // persistent work queue counter

// pre-transposed, tf32-rounded W image: [16 ktiles][192 n][68 pitch] floats
// (n = mat*64 + col; row n holds W[k][col] for k in the 64-wide k-tile)
#define WT_TILE_F 13056              // 192 * 68 floats per k-tile
__device__ __align__(16) float g_wt[16 * WT_TILE_F];

// ===========================================================================
// helpers (baseline PTX ISA, compiles for sm_100)
// ===========================================================================
__device__ __forceinline__ uint32_t smem_u32(const void* p) {
    uint32_t a;
    asm("{ .reg .u64 t; cvta.to.shared.u64 t, %1; cvt.u32.u64 %0, t; }" : "=r"(a) : "l"(p));
    return a;
}

#define MMATF32(d, a, b0, b1) \
    asm volatile("mma.sync.aligned.m16n8k8.row.col.f32.tf32.tf32.f32 " \
        "{%0,%1,%2,%3},{%4,%5,%6,%7},{%8,%9},{%0,%1,%2,%3};" \
        : "+f"((d)[0]), "+f"((d)[1]), "+f"((d)[2]), "+f"((d)[3]) \
        : "r"((a)[0]), "r"((a)[1]), "r"((a)[2]), "r"((a)[3]), "r"(b0), "r"(b1))

__device__ __forceinline__ float to_tf32(float x) {
    uint32_t u;
    asm("cvt.rna.tf32.f32 %0, %1;" : "=r"(u) : "f"(x));
    return __uint_as_float(u);
}
__device__ __forceinline__ uint32_t tf32_bits(float x) {
    uint32_t u;
    asm("cvt.rna.tf32.f32 %0, %1;" : "=r"(u) : "f"(x));
    return u;
}

#define CPA(dst, src) asm volatile("cp.async.ca.shared.global [%0], [%1], 16;" \
    :: "r"(dst), "l"(__cvta_generic_to_global(src)) : "memory")
#define CPC()  asm volatile("cp.async.commit_group;" ::: "memory")
#define CPW(n) asm volatile("cp.async.wait_group %0;" :: "n"(n) : "memory")

// ===========================================================================
// Kernel 0: transpose + tf32-round W into the padded global image.
// ===========================================================================
__global__ __launch_bounds__(256)
void wprep_kernel(const float* __restrict__ Wq,
                  const float* __restrict__ Wk,
                  const float* __restrict__ Wv)
{
    int idx = blockIdx.x * 256 + threadIdx.x;   // 0 .. 196607
    int n = idx >> 10;                          // 0..191
    int k = idx & 1023;                         // 0..1023
    int mat = n >> 6;
    int col = n & 63;
    const float* W = (mat == 0) ? Wq : (mat == 1) ? Wk : Wv;
    float v = W[(size_t)k * HS_ + col];
    g_wt[(size_t)(k >> 6) * WT_TILE_F + n * 68 + (k & 63)] = to_tf32(v);
}

// ===========================================================================
// Kernel 1: QKV projection, single-pass tf32 mma.sync m16n8k8.
// Block: 64 rows x 192 cols (q|k|v). 8 warps = 4 m-strips x 2 n-halves(96).
// Per warp per k-tile(64): 8 k-steps x 12 n-frags = 96 MMAs (vs 144 bf16).
// Double-buffered cp.async staging (R10-proven skeleton): Wt tile raw from
// g_wt image, x tile raw fp32; A-frags rna-rounded at register load.
// smem: 2 x (Wt 52224B + xs 17408B) = 139264B.
// ===========================================================================
#define WT_OFF 0
#define XS_OFF 52224
#define BUFSZ  69632
#define QKV_SMEM (2 * BUFSZ)

__global__ __launch_bounds__(256, 1)
void qkv_tf32_kernel(const float* __restrict__ x)
{
    extern __shared__ char sm[];
    const uint32_t sb = smem_u32(sm);

    if (blockIdx.x == 0 && threadIdx.x == 0) g_ctr = 0;   // reset attn queue

    const int tx   = threadIdx.x;
    const int wid  = tx >> 5;
    const int lane = tx & 31;
    const int row0 = blockIdx.x * 64;

    const int warp_m = wid & 3;        // 4 m-strips of 16
    const int warp_n = wid >> 2;       // 2 n-strips of 96
    const int wr0 = warp_m * 16;
    const int wn0 = warp_n * 96;

    const int gid = lane >> 2, tig = lane & 3;

    float acc[12][4] = {};

    // ---- prologue: issue tile 0 into buf0
    {
        const float* wsrc = g_wt;
        #pragma unroll
        for (int p = 0; p < 13; p++) {
            int ch = tx + 256 * p;
            if (ch < 3264) CPA(sb + WT_OFF + ch * 16, wsrc + ch * 4);
        }
        #pragma unroll
        for (int p = 0; p < 4; p++) {
            int ch = tx + 256 * p;
            int r = ch >> 4, c = ch & 15;
            CPA(sb + XS_OFF + r * 272 + c * 16, x + (size_t)(row0 + r) * HID_ + c * 4);
        }
        CPC();
    }

    for (int kt = 0; kt < 16; kt++) {
        const uint32_t cur = (kt & 1) * BUFSZ;
        const uint32_t nxt = ((kt + 1) & 1) * BUFSZ;

        CPW(0);            // tile kt landed (this thread's copies)
        __syncthreads();   // + all threads finished reading the other buffer

        if (kt < 15) {
            const float* wsrc = g_wt + (size_t)(kt + 1) * WT_TILE_F;
            const int k1 = (kt + 1) * 64;
            #pragma unroll
            for (int p = 0; p < 13; p++) {
                int ch = tx + 256 * p;
                if (ch < 3264) CPA(sb + nxt + WT_OFF + ch * 16, wsrc + ch * 4);
            }
            #pragma unroll
            for (int p = 0; p < 4; p++) {
                int ch = tx + 256 * p;
                int r = ch >> 4, c = ch & 15;
                CPA(sb + nxt + XS_OFF + r * 272 + c * 16,
                    x + (size_t)(row0 + r) * HID_ + k1 + c * 4);
            }
            CPC();
        }

        // ---- A fragments for this k-tile (rna-rounded to tf32)
        uint32_t af[8][4];
        {
            const char* xbase = sm + cur + XS_OFF;
            const int r = wr0 + gid;
            #pragma unroll
            for (int kc = 0; kc < 8; kc++) {
                const int k = kc * 8 + tig;
                af[kc][0] = tf32_bits(*(const float*)(xbase + r * 272 + k * 4));
                af[kc][1] = tf32_bits(*(const float*)(xbase + (r + 8) * 272 + k * 4));
                af[kc][2] = tf32_bits(*(const float*)(xbase + r * 272 + (k + 4) * 4));
                af[kc][3] = tf32_bits(*(const float*)(xbase + (r + 8) * 272 + (k + 4) * 4));
            }
        }

        // ---- 8 k-steps x 12 n-frags of tf32 MMA
        const uint32_t* Wt = (const uint32_t*)(sm + cur + WT_OFF);
        #pragma unroll
        for (int kc = 0; kc < 8; kc++) {
            #pragma unroll
            for (int nt = 0; nt < 12; nt++) {
                const uint32_t* wp = Wt + (wn0 + nt * 8 + gid) * 68 + kc * 8 + tig;
                MMATF32(acc[nt], af[kc], wp[0], wp[4]);
            }
        }
    }

    // epilogue: tf32-round; q scaled; v transposed [B][HS][T]
    const int r_lo = row0 + wr0 + gid;
    #pragma unroll
    for (int nt = 0; nt < 12; nt++) {
        int nglob = wn0 + nt * 8 + tig * 2;
        int mat = nglob >> 6;
        int col = nglob & 63;
        if (mat < 2) {
            float sc = (mat == 0) ? 0.03125f : 1.0f;
            float* dst = (mat == 0 ? g_q : g_k);
            float2 v0 = { to_tf32(acc[nt][0] * sc), to_tf32(acc[nt][1] * sc) };
            float2 v1 = { to_tf32(acc[nt][2] * sc), to_tf32(acc[nt][3] * sc) };
            *(float2*)(dst + (size_t)r_lo * HS_ + col)       = v0;
            *(float2*)(dst + (size_t)(r_lo + 8) * HS_ + col) = v1;
        } else {
            int bb = r_lo >> 11, tl = r_lo & 2047;
            float* dst = g_v + (size_t)bb * HS_ * T_;
            dst[(size_t)col * T_ + tl]           = to_tf32(acc[nt][0]);
            dst[(size_t)(col + 1) * T_ + tl]     = to_tf32(acc[nt][1]);
            dst[(size_t)col * T_ + tl + 8]       = to_tf32(acc[nt][2]);
            dst[(size_t)(col + 1) * T_ + tl + 8] = to_tf32(acc[nt][3]);
        }
    }
}

// ===========================================================================
// Kernel 2: causal attention on tf32 mma.sync. 148 persistent blocks (1/SM,
// balanced LPT) with race-free TRIPLE-buffered K/V (R10-proven, unchanged).
// ===========================================================================
#define PITCH  68
#define TILE_B (64 * PITCH * 4)         // 17408
#define OFF_KB 0                        // 3 K buffers
#define OFF_VB (3 * TILE_B)             // 3 V buffers
#define OFF_P  (6 * TILE_B)
#define OFF_X  (7 * TILE_B)             // 128 floats of l-exchange
#define OFF_TS (OFF_X + 512)
#define ATTN_SMEM (OFF_TS + 16)         // 122384
#define NTASKS 256

__global__ __launch_bounds__(256, 1)
void attn_tc_kernel(float* __restrict__ out)
{
    extern __shared__ char sm[];
    const uint32_t sb = smem_u32(sm);
    float* xb = (float*)(sm + OFF_X);
    int* tslot = (int*)(sm + OFF_TS);

    const int tx = threadIdx.x, wid = tx >> 5, lane = tx & 31;
    const int strip = wid >> 1, wn = wid & 1;
    const int gid = lane >> 2, tig = lane & 3;

    for (;;) {
        __syncthreads();                 // prior task fully done (incl. PV reads)
        if (tx == 0) *tslot = atomicAdd(&g_ctr, 1);
        __syncthreads();
        const int t = *tslot;
        if (t >= NTASKS) break;

        const int it = 31 - (t >> 3);          // LPT: big tasks first
        const int b  = t & 7;
        const int i0 = it * 64;

        const float* __restrict__ qb  = g_q + (size_t)b * T_ * HS_;
        const float* __restrict__ kb  = g_k + (size_t)b * T_ * HS_;
        const float* __restrict__ vtb = g_v + (size_t)b * HS_ * T_;

        // prologue: prefetch KV(0) and (if present) KV(1) into bufs 0, 1
        #pragma unroll
        for (int pre = 0; pre < 2; pre++) {
            if (pre > it) break;
            const uint32_t ko = OFF_KB + pre * TILE_B;
            const uint32_t vo = OFF_VB + pre * TILE_B;
            const int j0 = pre * 64;
            #pragma unroll
            for (int p = 0; p < 4; p++) {
                int idx = tx + 256 * p;
                int r = idx >> 4, c = idx & 15;
                CPA(sb + ko + r * 272 + c * 16, kb + (size_t)(j0 + r) * HS_ + c * 4);
                CPA(sb + vo + r * 272 + c * 16, vtb + (size_t)r * T_ + j0 + c * 4);
            }
            CPC();
        }

        uint32_t qf[8][4];
        {
            const int r = i0 + strip * 16 + gid;
            #pragma unroll
            for (int kc = 0; kc < 8; kc++) {
                qf[kc][0] = __float_as_uint(qb[(size_t)r * HS_ + kc * 8 + tig]);
                qf[kc][1] = __float_as_uint(qb[(size_t)(r + 8) * HS_ + kc * 8 + tig]);
                qf[kc][2] = __float_as_uint(qb[(size_t)r * HS_ + kc * 8 + tig + 4]);
                qf[kc][3] = __float_as_uint(qb[(size_t)(r + 8) * HS_ + kc * 8 + tig + 4]);
            }
        }

        float oacc[4][4] = {};
        float l0 = 0.f, l1 = 0.f;
        int bi = 0;                      // buffer holding tile j

        for (int j = 0; j <= it; j++) {
            if (j < it) { CPW(1); } else { CPW(0); }   // KV(j) landed
            __syncthreads();   // + all threads done with PV reads of j-1

            if (j + 2 <= it) {
                int pb = bi - 1; if (pb < 0) pb += 3;  // (bi+2)%3, free per barrier
                const uint32_t ko = OFF_KB + pb * TILE_B;
                const uint32_t vo = OFF_VB + pb * TILE_B;
                const int j2 = (j + 2) * 64;
                #pragma unroll
                for (int p = 0; p < 4; p++) {
                    int idx = tx + 256 * p;
                    int r = idx >> 4, c = idx & 15;
                    CPA(sb + ko + r * 272 + c * 16, kb + (size_t)(j2 + r) * HS_ + c * 4);
                    CPA(sb + vo + r * 272 + c * 16, vtb + (size_t)r * T_ + j2 + c * 4);
                }
                CPC();
            }

            const uint32_t* Kb = (const uint32_t*)(sm + OFF_KB + bi * TILE_B);
            const uint32_t* Vb = (const uint32_t*)(sm + OFF_VB + bi * TILE_B);

            float s[4][4] = {};
            #pragma unroll
            for (int kc = 0; kc < 8; kc++) {
                #pragma unroll
                for (int nf = 0; nf < 4; nf++) {
                    const uint32_t* kp = Kb + (wn * 32 + nf * 8 + gid) * PITCH + kc * 8 + tig;
                    MMATF32(s[nf], qf[kc], kp[0], kp[4]);
                }
            }

            uint32_t* Pp = (uint32_t*)(sm + OFF_P);
            #pragma unroll
            for (int nf = 0; nf < 4; nf++) {
                if (j == it) {
                    const int kk = wn * 32 + nf * 8 + tig * 2;
                    const int rr = strip * 16 + gid;
                    if (kk     > rr)     s[nf][0] = NEG_BIG;
                    if (kk + 1 > rr)     s[nf][1] = NEG_BIG;
                    if (kk     > rr + 8) s[nf][2] = NEG_BIG;
                    if (kk + 1 > rr + 8) s[nf][3] = NEG_BIG;
                }
                float p0 = __expf(s[nf][0]);
                float p1 = __expf(s[nf][1]);
                float p2 = __expf(s[nf][2]);
                float p3 = __expf(s[nf][3]);
                l0 += p0 + p1;
                l1 += p2 + p3;
                uint2 w0, w1;
                asm("cvt.rna.tf32.f32 %0, %1;" : "=r"(w0.x) : "f"(p0));
                asm("cvt.rna.tf32.f32 %0, %1;" : "=r"(w0.y) : "f"(p1));
                asm("cvt.rna.tf32.f32 %0, %1;" : "=r"(w1.x) : "f"(p2));
                asm("cvt.rna.tf32.f32 %0, %1;" : "=r"(w1.y) : "f"(p3));
                const int col = wn * 32 + nf * 8 + tig * 2;
                *(uint2*)(Pp + (strip * 16 + gid) * PITCH + col)     = w0;
                *(uint2*)(Pp + (strip * 16 + gid + 8) * PITCH + col) = w1;
            }
            __syncthreads();   // P visible to partner warps

            #pragma unroll
            for (int kc = 0; kc < 8; kc++) {
                uint32_t pa[4];
                const uint32_t* pp = Pp + (strip * 16 + gid) * PITCH + kc * 8 + tig;
                pa[0] = pp[0];
                pa[1] = pp[8 * PITCH];
                pa[2] = pp[4];
                pa[3] = pp[8 * PITCH + 4];
                #pragma unroll
                for (int nh = 0; nh < 4; nh++) {
                    const uint32_t* vp = Vb + (wn * 32 + nh * 8 + gid) * PITCH + kc * 8 + tig;
                    MMATF32(oacc[nh], pa, vp[0], vp[4]);
                }
            }
            bi = (bi + 1 == 3) ? 0 : bi + 1;
            // PV reads of this buffer protected by the barrier at top of j+1
        }

        l0 += __shfl_xor_sync(0xffffffffu, l0, 1);
        l0 += __shfl_xor_sync(0xffffffffu, l0, 2);
        l1 += __shfl_xor_sync(0xffffffffu, l1, 1);
        l1 += __shfl_xor_sync(0xffffffffu, l1, 2);
        if (tig == 0) {
            xb[(strip * 2 + wn) * 16 + gid]     = l0;
            xb[(strip * 2 + wn) * 16 + gid + 8] = l1;
        }
        __syncthreads();
        const float inv0 = 1.f / (l0 + xb[(strip * 2 + (wn ^ 1)) * 16 + gid]);
        const float inv1 = 1.f / (l1 + xb[(strip * 2 + (wn ^ 1)) * 16 + gid + 8]);

        float* ob = out + (size_t)b * T_ * HS_;
        const int r = i0 + strip * 16 + gid;
        #pragma unroll
        for (int nh = 0; nh < 4; nh++) {
            const int h = wn * 32 + nh * 8 + tig * 2;
            float2 v0 = { oacc[nh][0] * inv0, oacc[nh][1] * inv0 };
            float2 v1 = { oacc[nh][2] * inv1, oacc[nh][3] * inv1 };
            *(float2*)(ob + (size_t)r * HS_ + h)       = v0;
            *(float2*)(ob + (size_t)(r + 8) * HS_ + h) = v1;
        }
    }
}

// ===========================================================================
extern "C" void kernel_launch(void* const* d_in, const int* in_sizes, int n_in,
                              void* d_out, int out_size)
{
    const float* x  = (const float*)d_in[0];
    const float* Wq = (const float*)d_in[1];
    const float* Wk = (const float*)d_in[2];
    const float* Wv = (const float*)d_in[3];
    float* out = (float*)d_out;

    static bool configured = false;
    if (!configured) {
        cudaFuncSetAttribute(qkv_tf32_kernel,
                             cudaFuncAttributeMaxDynamicSharedMemorySize, QKV_SMEM);
        cudaFuncSetAttribute(attn_tc_kernel,
                             cudaFuncAttributeMaxDynamicSharedMemorySize, ATTN_SMEM);
        configured = true;
    }

    wprep_kernel<<<768, 256>>>(Wq, Wk, Wv);
    qkv_tf32_kernel<<<256, 256, QKV_SMEM>>>(x);
    attn_tc_kernel<<<148, 256, ATTN_SMEM>>>(out);
}

// round 13
// speedup vs baseline: 2.3704x; 1.5957x over previous
#include <cuda_runtime.h>
#include <cuda_fp16.h>
#include <cstdint>

#define B_   8
#define T_   2048
#define HID_ 1024
#define HS_  64
#define NEG_BIG (-3.0e38f)

// scratch (fp16): q [B][T][HS] (pre-scaled), k TRANSPOSED [B][HS][T], v [B][T][HS]
__device__ __half g_q[B_ * T_ * HS_];
__device__ __half g_k[B_ * T_ * HS_];
__device__ __half g_v[B_ * T_ * HS_];
__device__ int    g_ctr;             // persistent work queue counter

// fp16 W image in the R10-proven swizzled layout:
// [16 ktiles][24576 B] : 64 k-rows x 384 B (192 n x 2B), 16B-XOR swizzled
__device__ __align__(16) uint8_t g_wb[16 * 24576];

// ===========================================================================
// helpers (baseline PTX ISA, compiles for sm_100)
// ===========================================================================
__device__ __forceinline__ uint32_t smem_u32(const void* p) {
    uint32_t a;
    asm("{ .reg .u64 t; cvta.to.shared.u64 t, %1; cvt.u32.u64 %0, t; }" : "=r"(a) : "l"(p));
    return a;
}

#define LDSM_X4(r, addr) \
    asm volatile("ldmatrix.sync.aligned.m8n8.x4.shared.b16 {%0,%1,%2,%3}, [%4];" \
        : "=r"((r)[0]), "=r"((r)[1]), "=r"((r)[2]), "=r"((r)[3]) : "r"(addr))

#define LDSM_X4_T(r, addr) \
    asm volatile("ldmatrix.sync.aligned.m8n8.x4.trans.shared.b16 {%0,%1,%2,%3}, [%4];" \
        : "=r"((r)[0]), "=r"((r)[1]), "=r"((r)[2]), "=r"((r)[3]) : "r"(addr))

#define MMAF16(d, a, b0, b1) \
    asm volatile("mma.sync.aligned.m16n8k16.row.col.f32.f16.f16.f32 " \
        "{%0,%1,%2,%3},{%4,%5,%6,%7},{%8,%9},{%0,%1,%2,%3};" \
        : "+f"((d)[0]), "+f"((d)[1]), "+f"((d)[2]), "+f"((d)[3]) \
        : "r"((a)[0]), "r"((a)[1]), "r"((a)[2]), "r"((a)[3]), "r"(b0), "r"(b1))

#define CPA(dst, src) asm volatile("cp.async.ca.shared.global [%0], [%1], 16;" \
    :: "r"(dst), "l"(__cvta_generic_to_global(src)) : "memory")
#define CPC()  asm volatile("cp.async.commit_group;" ::: "memory")
#define CPW(n) asm volatile("cp.async.wait_group %0;" :: "n"(n) : "memory")

__device__ __forceinline__ uint2 f4_h4(float4 v) {
    __half2 a = __floats2half2_rn(v.x, v.y);
    __half2 b = __floats2half2_rn(v.z, v.w);
    uint2 r;
    r.x = *(uint32_t*)&a;
    r.y = *(uint32_t*)&b;
    return r;
}
__device__ __forceinline__ uint32_t pack_h2(float a, float b) {
    __half2 h = __floats2half2_rn(a, b);
    return *(uint32_t*)&h;
}

// ===========================================================================
// Kernel 0: W -> fp16 swizzled image (R10-proven layout, single image).
// ===========================================================================
__global__ __launch_bounds__(256)
void wprep_kernel(const float* __restrict__ Wq,
                  const float* __restrict__ Wk,
                  const float* __restrict__ Wv)
{
    int idx = blockIdx.x * 256 + threadIdx.x;     // 0..49151 float4s
    int mat = idx >> 14;
    int rem = idx & 16383;
    int k   = rem >> 4;
    int n4  = (rem & 15) << 2;
    const float* W = (mat == 0) ? Wq : (mat == 1) ? Wk : Wv;
    float4 v = *(const float4*)(W + (size_t)k * HS_ + n4);
    uint32_t byte = (uint32_t)((k >> 6) * 24576 + (k & 63) * 384
                  + ((mat * 128 + n4 * 2) ^ ((k & 7) << 4)));
    *(uint2*)(g_wb + byte) = f4_h4(v);
}

// ===========================================================================
// Kernel 1: QKV projection, single-pass fp16 mma m16n8k16.
// 64 rows x 192 cols per block; 8 warps = 4 m-strips x 2 n-halves(96).
// 48 MMAs/warp/ktile. R10-proven double-buffer skeleton + fragment paths.
// smem: 2 x (B 24576 + A 8192) = 65536.
// ===========================================================================
#define QB_OFF 0
#define QA_OFF 24576
#define QBUFSZ 32768
#define QKV_SMEM 65536

__global__ __launch_bounds__(256, 1)
void qkv_h_kernel(const float* __restrict__ x)
{
    extern __shared__ char sm[];
    const uint32_t sb = smem_u32(sm);

    if (blockIdx.x == 0 && threadIdx.x == 0) g_ctr = 0;   // reset attn queue

    const int tx   = threadIdx.x;
    const int wid  = tx >> 5;
    const int lane = tx & 31;
    const int row0 = blockIdx.x * 64;

    const int warp_m = wid & 3;
    const int warp_n = wid >> 2;
    const int wr0 = warp_m * 16;
    const int wn0 = warp_n * 96;

    const int a_r    = wr0 + (lane & 7) + ((lane >> 3) & 1) * 8;
    const int a_koff = (lane >> 4) << 3;
    const int a_xr   = (a_r & 7) << 4;

    const int b_k    = (lane & 7) + ((lane >> 3) & 1) * 8;
    const int b_n0   = wn0 + ((lane >> 4) << 3);
    const int b_xr   = (b_k & 7) << 4;

    float acc[12][4] = {};
    float4 px[4];

    // prologue: B(0) via cp.async; A(0) load+cvt+store
    #pragma unroll
    for (int p = 0; p < 6; p++) {
        int ch = tx + 256 * p;
        CPA(sb + QB_OFF + ch * 16, g_wb + ch * 16);
    }
    CPC();
    #pragma unroll
    for (int p = 0; p < 4; p++) {
        int idx = tx + 256 * p;
        px[p] = *(const float4*)(x + (size_t)(row0 + (idx >> 4)) * HID_ + ((idx & 15) << 2));
    }
    #pragma unroll
    for (int p = 0; p < 4; p++) {
        int idx = tx + 256 * p;
        int r = idx >> 4, c4 = (idx & 15) << 2;
        uint32_t byte = (uint32_t)(r * 128 + c4 * 2) ^ ((r & 7) << 4);
        *(uint2*)(sm + QA_OFF + byte) = f4_h4(px[p]);
    }

    for (int kt = 0; kt < 16; kt++) {
        const uint32_t cur = (kt & 1) * QBUFSZ;
        const uint32_t nxt = ((kt + 1) & 1) * QBUFSZ;

        CPW(0);
        __syncthreads();

        if (kt < 15) {
            const uint8_t* src = g_wb + (size_t)(kt + 1) * 24576;
            #pragma unroll
            for (int p = 0; p < 6; p++) {
                int ch = tx + 256 * p;
                CPA(sb + nxt + QB_OFF + ch * 16, src + ch * 16);
            }
            CPC();
            const int k1 = (kt + 1) * 64;
            #pragma unroll
            for (int p = 0; p < 4; p++) {
                int idx = tx + 256 * p;
                px[p] = *(const float4*)(x + (size_t)(row0 + (idx >> 4)) * HID_ + k1 + ((idx & 15) << 2));
            }
        }

        #pragma unroll
        for (int ks = 0; ks < 4; ks++) {
            const int kk = ks * 16 + a_koff;
            const uint32_t aoff = ((uint32_t)(a_r * 128 + kk * 2) ^ a_xr);
            uint32_t ah[4];
            LDSM_X4(ah, sb + cur + QA_OFF + aoff);

            const int bk = ks * 16 + b_k;
            #pragma unroll
            for (int pr = 0; pr < 6; pr++) {
                const int n = b_n0 + pr * 16;
                const uint32_t boff = ((uint32_t)(bk * 384 + n * 2) ^ b_xr);
                uint32_t bh[4];
                LDSM_X4_T(bh, sb + cur + QB_OFF + boff);
                MMAF16(acc[2 * pr],     ah, bh[0], bh[1]);
                MMAF16(acc[2 * pr + 1], ah, bh[2], bh[3]);
            }
        }

        if (kt < 15) {
            #pragma unroll
            for (int p = 0; p < 4; p++) {
                int idx = tx + 256 * p;
                int r = idx >> 4, c4 = (idx & 15) << 2;
                uint32_t byte = ((uint32_t)(r * 128 + c4 * 2) ^ ((r & 7) << 4));
                *(uint2*)(sm + nxt + QA_OFF + byte) = f4_h4(px[p]);
            }
        }
    }

    // epilogue: fp16 stores; q scaled; k transposed [B][HS][T]; v natural
    const int r_lo = row0 + wr0 + (lane >> 2);
    #pragma unroll
    for (int nt = 0; nt < 12; nt++) {
        int nglob = wn0 + nt * 8 + (lane & 3) * 2;
        int mat = nglob >> 6;
        int col = nglob & 63;
        if (mat == 0) {
            const float sc = 0.03125f;
            uint32_t h0 = pack_h2(acc[nt][0] * sc, acc[nt][1] * sc);
            uint32_t h1 = pack_h2(acc[nt][2] * sc, acc[nt][3] * sc);
            *(uint32_t*)(g_q + (size_t)r_lo * HS_ + col)       = h0;
            *(uint32_t*)(g_q + (size_t)(r_lo + 8) * HS_ + col) = h1;
        } else if (mat == 1) {
            int bb = r_lo >> 11, tl = r_lo & 2047;
            __half* dk = g_k + (size_t)bb * HS_ * T_;
            dk[(size_t)col * T_ + tl]           = __float2half_rn(acc[nt][0]);
            dk[(size_t)(col + 1) * T_ + tl]     = __float2half_rn(acc[nt][1]);
            dk[(size_t)col * T_ + tl + 8]       = __float2half_rn(acc[nt][2]);
            dk[(size_t)(col + 1) * T_ + tl + 8] = __float2half_rn(acc[nt][3]);
        } else {
            uint32_t h0 = pack_h2(acc[nt][0], acc[nt][1]);
            uint32_t h1 = pack_h2(acc[nt][2], acc[nt][3]);
            *(uint32_t*)(g_v + (size_t)r_lo * HS_ + col)       = h0;
            *(uint32_t*)(g_v + (size_t)(r_lo + 8) * HS_ + col) = h1;
        }
    }
}

// ===========================================================================
// Kernel 2: causal attention, fp16 mma m16n8k16. 148 persistent blocks
// (balanced LPT), race-free triple-buffered K/V (R10-proven skeleton).
// K tiles [hs][key] (from transposed g_k), V tiles [key][hs] (natural),
// Q & P tiles [row][64] fp16, all 128B rows with 16B-XOR swizzle.
// smem: Q 8K | 3xK 24K | 3xV 24K | P 8K | xb | ts  = 66064 B.
// ===========================================================================
#define KTILE  8192
#define OFF_Q  0
#define OFF_KB 8192
#define OFF_VB 32768
#define OFF_P  57344
#define OFF_X  65536
#define OFF_TS 66048
#define ATTN_SMEM 66064
#define NTASKS 256

__device__ __forceinline__ void stage_kv(uint32_t sb, const __half* kh, const __half* vh,
                                         int jj, int pb, int tx)
{
    #pragma unroll
    for (int p = 0; p < 2; p++) {
        int ch = tx + 256 * p;               // 0..511
        int r = ch >> 3, c = ch & 7;
        uint32_t sw = (uint32_t)(r * 128 + c * 16) ^ ((r & 7) << 4);
        CPA(sb + OFF_KB + pb * KTILE + sw, kh + (size_t)r * T_ + jj + c * 8);
        CPA(sb + OFF_VB + pb * KTILE + sw, vh + (size_t)(jj + r) * HS_ + c * 8);
    }
}

__global__ __launch_bounds__(256, 1)
void attn_h_kernel(float* __restrict__ out)
{
    extern __shared__ char sm[];
    const uint32_t sb = smem_u32(sm);
    float* xb = (float*)(sm + OFF_X);
    int* tslot = (int*)(sm + OFF_TS);

    const int tx = threadIdx.x, wid = tx >> 5, lane = tx & 31;
    const int strip = wid >> 1, wn = wid & 1;
    const int gid = lane >> 2, tig = lane & 3;

    const int a_r    = strip * 16 + (lane & 7) + ((lane >> 3) & 1) * 8;
    const int a_koff = (lane >> 4) << 3;
    const int a_xr   = (a_r & 7) << 4;
    const int b_k    = (lane & 7) + ((lane >> 3) & 1) * 8;
    const int b_n0   = wn * 32 + ((lane >> 4) << 3);
    const int b_xr   = (b_k & 7) << 4;

    for (;;) {
        __syncthreads();                 // prior task fully done (incl. PV reads)
        if (tx == 0) *tslot = atomicAdd(&g_ctr, 1);
        __syncthreads();
        const int t = *tslot;
        if (t >= NTASKS) break;

        const int it = 31 - (t >> 3);          // LPT: big tasks first
        const int b  = t & 7;
        const int i0 = it * 64;

        const __half* __restrict__ qh = g_q + (size_t)b * T_ * HS_;
        const __half* __restrict__ kh = g_k + (size_t)b * HS_ * T_;
        const __half* __restrict__ vh = g_v + (size_t)b * T_ * HS_;

        // group0: Q + KV(0);  group1: KV(1) if present
        #pragma unroll
        for (int p = 0; p < 2; p++) {
            int ch = tx + 256 * p;
            int r = ch >> 3, c = ch & 7;
            uint32_t sw = (uint32_t)(r * 128 + c * 16) ^ ((r & 7) << 4);
            CPA(sb + OFF_Q + sw, qh + (size_t)(i0 + r) * HS_ + c * 8);
        }
        stage_kv(sb, kh, vh, 0, 0, tx);
        CPC();
        if (it >= 1) { stage_kv(sb, kh, vh, 64, 1, tx); CPC(); }

        if (it >= 1) { CPW(1); } else { CPW(0); }   // Q + KV(0) landed
        __syncthreads();

        uint32_t qf[4][4];
        #pragma unroll
        for (int ks = 0; ks < 4; ks++) {
            const int kk = ks * 16 + a_koff;
            LDSM_X4(qf[ks], sb + OFF_Q + ((uint32_t)(a_r * 128 + kk * 2) ^ a_xr));
        }

        float oacc[4][4] = {};
        float l0 = 0.f, l1 = 0.f;
        int bi = 0;

        for (int j = 0; j <= it; j++) {
            if (j < it) { CPW(1); } else { CPW(0); }   // KV(j) landed
            __syncthreads();   // + all threads done with PV reads of j-1

            if (j + 2 <= it) {
                int pb = bi - 1; if (pb < 0) pb += 3;  // free per the barrier above
                stage_kv(sb, kh, vh, (j + 2) * 64, pb, tx);
                CPC();
            }

            const uint32_t Kb = sb + OFF_KB + bi * KTILE;
            const uint32_t Vb = sb + OFF_VB + bi * KTILE;

            // S = Q K^T
            float s[4][4] = {};
            #pragma unroll
            for (int ks = 0; ks < 4; ks++) {
                const int bk = ks * 16 + b_k;
                #pragma unroll
                for (int g = 0; g < 2; g++) {
                    const int n = b_n0 + g * 16;
                    uint32_t bh[4];
                    LDSM_X4_T(bh, Kb + ((uint32_t)(bk * 128 + n * 2) ^ b_xr));
                    MMAF16(s[2 * g],     qf[ks], bh[0], bh[1]);
                    MMAF16(s[2 * g + 1], qf[ks], bh[2], bh[3]);
                }
            }

            // mask + exp + P(fp16) store + partial l
            #pragma unroll
            for (int nf = 0; nf < 4; nf++) {
                if (j == it) {
                    const int kk = wn * 32 + nf * 8 + tig * 2;
                    const int rr = strip * 16 + gid;
                    if (kk     > rr)     s[nf][0] = NEG_BIG;
                    if (kk + 1 > rr)     s[nf][1] = NEG_BIG;
                    if (kk     > rr + 8) s[nf][2] = NEG_BIG;
                    if (kk + 1 > rr + 8) s[nf][3] = NEG_BIG;
                }
                float p0 = __expf(s[nf][0]);
                float p1 = __expf(s[nf][1]);
                float p2 = __expf(s[nf][2]);
                float p3 = __expf(s[nf][3]);
                l0 += p0 + p1;
                l1 += p2 + p3;
                const int col = wn * 32 + nf * 8 + tig * 2;
                const int r = strip * 16 + gid;
                *(uint32_t*)(sm + OFF_P + ((uint32_t)(r * 128 + col * 2) ^ ((r & 7) << 4)))
                    = pack_h2(p0, p1);
                *(uint32_t*)(sm + OFF_P + ((uint32_t)((r + 8) * 128 + col * 2) ^ ((r & 7) << 4)))
                    = pack_h2(p2, p3);
            }
            __syncthreads();   // P visible to partner warps

            // O += P V
            #pragma unroll
            for (int ks = 0; ks < 4; ks++) {
                const int kk = ks * 16 + a_koff;
                uint32_t pa[4];
                LDSM_X4(pa, sb + OFF_P + ((uint32_t)(a_r * 128 + kk * 2) ^ a_xr));
                const int bk = ks * 16 + b_k;
                #pragma unroll
                for (int g = 0; g < 2; g++) {
                    const int n = b_n0 + g * 16;
                    uint32_t bv[4];
                    LDSM_X4_T(bv, Vb + ((uint32_t)(bk * 128 + n * 2) ^ b_xr));
                    MMAF16(oacc[2 * g],     pa, bv[0], bv[1]);
                    MMAF16(oacc[2 * g + 1], pa, bv[2], bv[3]);
                }
            }
            bi = (bi + 1 == 3) ? 0 : bi + 1;
        }

        l0 += __shfl_xor_sync(0xffffffffu, l0, 1);
        l0 += __shfl_xor_sync(0xffffffffu, l0, 2);
        l1 += __shfl_xor_sync(0xffffffffu, l1, 1);
        l1 += __shfl_xor_sync(0xffffffffu, l1, 2);
        if (tig == 0) {
            xb[(strip * 2 + wn) * 16 + gid]     = l0;
            xb[(strip * 2 + wn) * 16 + gid + 8] = l1;
        }
        __syncthreads();
        const float inv0 = 1.f / (l0 + xb[(strip * 2 + (wn ^ 1)) * 16 + gid]);
        const float inv1 = 1.f / (l1 + xb[(strip * 2 + (wn ^ 1)) * 16 + gid + 8]);

        float* ob = out + (size_t)b * T_ * HS_;
        const int r = i0 + strip * 16 + gid;
        #pragma unroll
        for (int nh = 0; nh < 4; nh++) {
            const int h = wn * 32 + nh * 8 + tig * 2;
            float2 v0 = { oacc[nh][0] * inv0, oacc[nh][1] * inv0 };
            float2 v1 = { oacc[nh][2] * inv1, oacc[nh][3] * inv1 };
            *(float2*)(ob + (size_t)r * HS_ + h)       = v0;
            *(float2*)(ob + (size_t)(r + 8) * HS_ + h) = v1;
        }
    }
}

// ===========================================================================
extern "C" void kernel_launch(void* const* d_in, const int* in_sizes, int n_in,
                              void* d_out, int out_size)
{
    const float* x  = (const float*)d_in[0];
    const float* Wq = (const float*)d_in[1];
    const float* Wk = (const float*)d_in[2];
    const float* Wv = (const float*)d_in[3];
    float* out = (float*)d_out;

    static bool configured = false;
    if (!configured) {
        cudaFuncSetAttribute(qkv_h_kernel,
                             cudaFuncAttributeMaxDynamicSharedMemorySize, QKV_SMEM);
        cudaFuncSetAttribute(attn_h_kernel,
                             cudaFuncAttributeMaxDynamicSharedMemorySize, ATTN_SMEM);
        configured = true;
    }

    wprep_kernel<<<192, 256>>>(Wq, Wk, Wv);
    qkv_h_kernel<<<256, 256, QKV_SMEM>>>(x);
    attn_h_kernel<<<148, 256, ATTN_SMEM>>>(out);
}

// round 14
// speedup vs baseline: 2.5140x; 1.0606x over previous
#include <cuda_runtime.h>
#include <cuda_fp16.h>
#include <cstdint>

#define B_   8
#define T_   2048
#define HID_ 1024
#define HS_  64
#define NEG_BIG (-3.0e38f)

// scratch (fp16): q [B][T][HS] (pre-scaled), k TRANSPOSED [B][HS][T], v [B][T][HS]
__device__ __half g_q[B_ * T_ * HS_];
__device__ __half g_k[B_ * T_ * HS_];
__device__ __half g_v[B_ * T_ * HS_];

// fp16 W image in the R10-proven swizzled layout:
// [16 ktiles][24576 B] : 64 k-rows x 384 B (192 n x 2B), 16B-XOR swizzled
__device__ __align__(16) uint8_t g_wb[16 * 24576];

// ===========================================================================
// helpers (baseline PTX ISA, compiles for sm_100)
// ===========================================================================
__device__ __forceinline__ uint32_t smem_u32(const void* p) {
    uint32_t a;
    asm("{ .reg .u64 t; cvta.to.shared.u64 t, %1; cvt.u32.u64 %0, t; }" : "=r"(a) : "l"(p));
    return a;
}

#define LDSM_X4(r, addr) \
    asm volatile("ldmatrix.sync.aligned.m8n8.x4.shared.b16 {%0,%1,%2,%3}, [%4];" \
        : "=r"((r)[0]), "=r"((r)[1]), "=r"((r)[2]), "=r"((r)[3]) : "r"(addr))

#define LDSM_X4_T(r, addr) \
    asm volatile("ldmatrix.sync.aligned.m8n8.x4.trans.shared.b16 {%0,%1,%2,%3}, [%4];" \
        : "=r"((r)[0]), "=r"((r)[1]), "=r"((r)[2]), "=r"((r)[3]) : "r"(addr))

#define MMAF16(d, a, b0, b1) \
    asm volatile("mma.sync.aligned.m16n8k16.row.col.f32.f16.f16.f32 " \
        "{%0,%1,%2,%3},{%4,%5,%6,%7},{%8,%9},{%0,%1,%2,%3};" \
        : "+f"((d)[0]), "+f"((d)[1]), "+f"((d)[2]), "+f"((d)[3]) \
        : "r"((a)[0]), "r"((a)[1]), "r"((a)[2]), "r"((a)[3]), "r"(b0), "r"(b1))

#define CPA(dst, src) asm volatile("cp.async.ca.shared.global [%0], [%1], 16;" \
    :: "r"(dst), "l"(__cvta_generic_to_global(src)) : "memory")
#define CPC()  asm volatile("cp.async.commit_group;" ::: "memory")
#define CPW(n) asm volatile("cp.async.wait_group %0;" :: "n"(n) : "memory")

__device__ __forceinline__ uint2 f4_h4(float4 v) {
    __half2 a = __floats2half2_rn(v.x, v.y);
    __half2 b = __floats2half2_rn(v.z, v.w);
    uint2 r;
    r.x = *(uint32_t*)&a;
    r.y = *(uint32_t*)&b;
    return r;
}
__device__ __forceinline__ uint32_t pack_h2(float a, float b) {
    __half2 h = __floats2half2_rn(a, b);
    return *(uint32_t*)&h;
}

// ===========================================================================
// Kernel 0: W -> fp16 swizzled image (R13 verbatim).
// ===========================================================================
__global__ __launch_bounds__(256)
void wprep_kernel(const float* __restrict__ Wq,
                  const float* __restrict__ Wk,
                  const float* __restrict__ Wv)
{
    int idx = blockIdx.x * 256 + threadIdx.x;     // 0..49151 float4s
    int mat = idx >> 14;
    int rem = idx & 16383;
    int k   = rem >> 4;
    int n4  = (rem & 15) << 2;
    const float* W = (mat == 0) ? Wq : (mat == 1) ? Wk : Wv;
    float4 v = *(const float4*)(W + (size_t)k * HS_ + n4);
    uint32_t byte = (uint32_t)((k >> 6) * 24576 + (k & 63) * 384
                  + ((mat * 128 + n4 * 2) ^ ((k & 7) << 4)));
    *(uint2*)(g_wb + byte) = f4_h4(v);
}

// ===========================================================================
// Kernel 1: QKV projection, single-pass fp16 mma m16n8k16 (R13 verbatim).
// ===========================================================================
#define QB_OFF 0
#define QA_OFF 24576
#define QBUFSZ 32768
#define QKV_SMEM 65536

__global__ __launch_bounds__(256, 1)
void qkv_h_kernel(const float* __restrict__ x)
{
    extern __shared__ char sm[];
    const uint32_t sb = smem_u32(sm);

    const int tx   = threadIdx.x;
    const int wid  = tx >> 5;
    const int lane = tx & 31;
    const int row0 = blockIdx.x * 64;

    const int warp_m = wid & 3;
    const int warp_n = wid >> 2;
    const int wr0 = warp_m * 16;
    const int wn0 = warp_n * 96;

    const int a_r    = wr0 + (lane & 7) + ((lane >> 3) & 1) * 8;
    const int a_koff = (lane >> 4) << 3;
    const int a_xr   = (a_r & 7) << 4;

    const int b_k    = (lane & 7) + ((lane >> 3) & 1) * 8;
    const int b_n0   = wn0 + ((lane >> 4) << 3);
    const int b_xr   = (b_k & 7) << 4;

    float acc[12][4] = {};
    float4 px[4];

    // prologue: B(0) via cp.async; A(0) load+cvt+store
    #pragma unroll
    for (int p = 0; p < 6; p++) {
        int ch = tx + 256 * p;
        CPA(sb + QB_OFF + ch * 16, g_wb + ch * 16);
    }
    CPC();
    #pragma unroll
    for (int p = 0; p < 4; p++) {
        int idx = tx + 256 * p;
        px[p] = *(const float4*)(x + (size_t)(row0 + (idx >> 4)) * HID_ + ((idx & 15) << 2));
    }
    #pragma unroll
    for (int p = 0; p < 4; p++) {
        int idx = tx + 256 * p;
        int r = idx >> 4, c4 = (idx & 15) << 2;
        uint32_t byte = (uint32_t)(r * 128 + c4 * 2) ^ ((r & 7) << 4);
        *(uint2*)(sm + QA_OFF + byte) = f4_h4(px[p]);
    }

    for (int kt = 0; kt < 16; kt++) {
        const uint32_t cur = (kt & 1) * QBUFSZ;
        const uint32_t nxt = ((kt + 1) & 1) * QBUFSZ;

        CPW(0);
        __syncthreads();

        if (kt < 15) {
            const uint8_t* src = g_wb + (size_t)(kt + 1) * 24576;
            #pragma unroll
            for (int p = 0; p < 6; p++) {
                int ch = tx + 256 * p;
                CPA(sb + nxt + QB_OFF + ch * 16, src + ch * 16);
            }
            CPC();
            const int k1 = (kt + 1) * 64;
            #pragma unroll
            for (int p = 0; p < 4; p++) {
                int idx = tx + 256 * p;
                px[p] = *(const float4*)(x + (size_t)(row0 + (idx >> 4)) * HID_ + k1 + ((idx & 15) << 2));
            }
        }

        #pragma unroll
        for (int ks = 0; ks < 4; ks++) {
            const int kk = ks * 16 + a_koff;
            const uint32_t aoff = ((uint32_t)(a_r * 128 + kk * 2) ^ a_xr);
            uint32_t ah[4];
            LDSM_X4(ah, sb + cur + QA_OFF + aoff);

            const int bk = ks * 16 + b_k;
            #pragma unroll
            for (int pr = 0; pr < 6; pr++) {
                const int n = b_n0 + pr * 16;
                const uint32_t boff = ((uint32_t)(bk * 384 + n * 2) ^ b_xr);
                uint32_t bh[4];
                LDSM_X4_T(bh, sb + cur + QB_OFF + boff);
                MMAF16(acc[2 * pr],     ah, bh[0], bh[1]);
                MMAF16(acc[2 * pr + 1], ah, bh[2], bh[3]);
            }
        }

        if (kt < 15) {
            #pragma unroll
            for (int p = 0; p < 4; p++) {
                int idx = tx + 256 * p;
                int r = idx >> 4, c4 = (idx & 15) << 2;
                uint32_t byte = ((uint32_t)(r * 128 + c4 * 2) ^ ((r & 7) << 4));
                *(uint2*)(sm + nxt + QA_OFF + byte) = f4_h4(px[p]);
            }
        }
    }

    // epilogue: fp16 stores; q scaled; k transposed [B][HS][T]; v natural
    const int r_lo = row0 + wr0 + (lane >> 2);
    #pragma unroll
    for (int nt = 0; nt < 12; nt++) {
        int nglob = wn0 + nt * 8 + (lane & 3) * 2;
        int mat = nglob >> 6;
        int col = nglob & 63;
        if (mat == 0) {
            const float sc = 0.03125f;
            uint32_t h0 = pack_h2(acc[nt][0] * sc, acc[nt][1] * sc);
            uint32_t h1 = pack_h2(acc[nt][2] * sc, acc[nt][3] * sc);
            *(uint32_t*)(g_q + (size_t)r_lo * HS_ + col)       = h0;
            *(uint32_t*)(g_q + (size_t)(r_lo + 8) * HS_ + col) = h1;
        } else if (mat == 1) {
            int bb = r_lo >> 11, tl = r_lo & 2047;
            __half* dk = g_k + (size_t)bb * HS_ * T_;
            dk[(size_t)col * T_ + tl]           = __float2half_rn(acc[nt][0]);
            dk[(size_t)(col + 1) * T_ + tl]     = __float2half_rn(acc[nt][1]);
            dk[(size_t)col * T_ + tl + 8]       = __float2half_rn(acc[nt][2]);
            dk[(size_t)(col + 1) * T_ + tl + 8] = __float2half_rn(acc[nt][3]);
        } else {
            uint32_t h0 = pack_h2(acc[nt][0], acc[nt][1]);
            uint32_t h1 = pack_h2(acc[nt][2], acc[nt][3]);
            *(uint32_t*)(g_v + (size_t)r_lo * HS_ + col)       = h0;
            *(uint32_t*)(g_v + (size_t)(r_lo + 8) * HS_ + col) = h1;
        }
    }
}

// ===========================================================================
// Kernel 2: causal attention, fp16 mma, FA2-style register pipeline.
// CTA = 128 threads = 4 warps; each warp owns 16 query rows x ALL 64 keys.
// S->P A-frags built by register packing (C-frag == A-frag lane layout,
// verified against the hardware-proven LDSM path). No P smem, ONE barrier
// per key-tile (KV rotation; race-free per the R10/R13 argument).
// 2 CTAs/SM; static anti-paired schedule: block b<148 -> task b (LPT desc),
// block 148+j -> task 255-j, so mod-148 SM pairs sum to ~const work.
// smem: Q 8K | 3xK 8K | 3xV 8K = 57344 B.
// ===========================================================================
#define KTILE  8192
#define OFF_Q  0
#define OFF_KB 8192
#define OFF_VB 32768
#define ATTN_SMEM 57344

__device__ __forceinline__ void stage_kv2(uint32_t sb, const __half* kh, const __half* vh,
                                          int jj, int pb, int tx)
{
    #pragma unroll
    for (int p = 0; p < 4; p++) {
        int ch = tx + 128 * p;               // 0..511 16B-chunks
        int r = ch >> 3, c = ch & 7;
        uint32_t sw = (uint32_t)(r * 128 + c * 16) ^ ((r & 7) << 4);
        CPA(sb + OFF_KB + pb * KTILE + sw, kh + (size_t)r * T_ + jj + c * 8);
        CPA(sb + OFF_VB + pb * KTILE + sw, vh + (size_t)(jj + r) * HS_ + c * 8);
    }
}

__global__ __launch_bounds__(128, 2)
void attn_h2_kernel(float* __restrict__ out)
{
    extern __shared__ char sm[];
    const uint32_t sb = smem_u32(sm);

    const int tx = threadIdx.x, wid = tx >> 5, lane = tx & 31;
    const int gid = lane >> 2, tig = lane & 3;

    const int bid = blockIdx.x;
    const int t = (bid < 148) ? bid : (403 - bid);   // anti-paired static map
    const int it = 31 - (t >> 3);                    // LPT desc in t
    const int b  = t & 7;
    const int i0 = it * 64;

    const int a_r    = wid * 16 + (lane & 7) + ((lane >> 3) & 1) * 8;
    const int a_koff = (lane >> 4) << 3;
    const int a_xr   = (a_r & 7) << 4;
    const int b_k    = (lane & 7) + ((lane >> 3) & 1) * 8;
    const int b_nb   = (lane >> 4) << 3;
    const int b_xr   = (b_k & 7) << 4;

    const __half* __restrict__ qh = g_q + (size_t)b * T_ * HS_;
    const __half* __restrict__ kh = g_k + (size_t)b * HS_ * T_;
    const __half* __restrict__ vh = g_v + (size_t)b * T_ * HS_;

    // group0: Q + KV(0);  group1: KV(1) if present
    #pragma unroll
    for (int p = 0; p < 4; p++) {
        int ch = tx + 128 * p;
        int r = ch >> 3, c = ch & 7;
        uint32_t sw = (uint32_t)(r * 128 + c * 16) ^ ((r & 7) << 4);
        CPA(sb + OFF_Q + sw, qh + (size_t)(i0 + r) * HS_ + c * 8);
    }
    stage_kv2(sb, kh, vh, 0, 0, tx);
    CPC();
    if (it >= 1) { stage_kv2(sb, kh, vh, 64, 1, tx); CPC(); }

    if (it >= 1) { CPW(1); } else { CPW(0); }   // Q + KV(0) landed
    __syncthreads();

    uint32_t qf[4][4];
    #pragma unroll
    for (int ks = 0; ks < 4; ks++) {
        const int kk = ks * 16 + a_koff;
        LDSM_X4(qf[ks], sb + OFF_Q + ((uint32_t)(a_r * 128 + kk * 2) ^ a_xr));
    }

    float oacc[8][4] = {};
    float l0 = 0.f, l1 = 0.f;
    int bi = 0;

    for (int j = 0; j <= it; j++) {
        if (j < it) { CPW(1); } else { CPW(0); }   // KV(j) landed
        __syncthreads();   // + all warps done with PV reads of j-1

        if (j + 2 <= it) {
            int pb = bi - 1; if (pb < 0) pb += 3;  // free per the barrier above
            stage_kv2(sb, kh, vh, (j + 2) * 64, pb, tx);
            CPC();
        }

        const uint32_t Kb = sb + OFF_KB + bi * KTILE;
        const uint32_t Vb = sb + OFF_VB + bi * KTILE;

        // S = Q K^T : 16 rows x 64 keys per warp
        float s[8][4] = {};
        #pragma unroll
        for (int ks = 0; ks < 4; ks++) {
            const int bk = ks * 16 + b_k;          // hs row of K^T tile
            #pragma unroll
            for (int g = 0; g < 4; g++) {
                const int n = g * 16 + b_nb;       // key col
                uint32_t bh[4];
                LDSM_X4_T(bh, Kb + ((uint32_t)(bk * 128 + n * 2) ^ b_xr));
                MMAF16(s[2 * g],     qf[ks], bh[0], bh[1]);
                MMAF16(s[2 * g + 1], qf[ks], bh[2], bh[3]);
            }
        }

        // mask (diagonal tile) + exp + partial l  (all in registers)
        #pragma unroll
        for (int nf = 0; nf < 8; nf++) {
            if (j == it) {
                const int kk = nf * 8 + tig * 2;
                const int rr = wid * 16 + gid;
                if (kk     > rr)     s[nf][0] = NEG_BIG;
                if (kk + 1 > rr)     s[nf][1] = NEG_BIG;
                if (kk     > rr + 8) s[nf][2] = NEG_BIG;
                if (kk + 1 > rr + 8) s[nf][3] = NEG_BIG;
            }
            s[nf][0] = __expf(s[nf][0]);
            s[nf][1] = __expf(s[nf][1]);
            s[nf][2] = __expf(s[nf][2]);
            s[nf][3] = __expf(s[nf][3]);
            l0 += s[nf][0] + s[nf][1];
            l1 += s[nf][2] + s[nf][3];
        }

        // O += P V : P A-frags by register packing (C-frag -> A-frag layout)
        #pragma unroll
        for (int kc = 0; kc < 4; kc++) {
            uint32_t pa[4];
            pa[0] = pack_h2(s[2 * kc][0],     s[2 * kc][1]);      // row gid,   k-lo
            pa[1] = pack_h2(s[2 * kc][2],     s[2 * kc][3]);      // row gid+8, k-lo
            pa[2] = pack_h2(s[2 * kc + 1][0], s[2 * kc + 1][1]);  // row gid,   k-hi
            pa[3] = pack_h2(s[2 * kc + 1][2], s[2 * kc + 1][3]);  // row gid+8, k-hi
            const int bk = kc * 16 + b_k;          // key row of V tile
            #pragma unroll
            for (int g = 0; g < 4; g++) {
                const int n = g * 16 + b_nb;       // hs col
                uint32_t bv[4];
                LDSM_X4_T(bv, Vb + ((uint32_t)(bk * 128 + n * 2) ^ b_xr));
                MMAF16(oacc[2 * g],     pa, bv[0], bv[1]);
                MMAF16(oacc[2 * g + 1], pa, bv[2], bv[3]);
            }
        }
        bi = (bi + 1 == 3) ? 0 : bi + 1;
    }

    // epilogue: l fully warp-local (quad reduce), normalize, store fp32
    l0 += __shfl_xor_sync(0xffffffffu, l0, 1);
    l0 += __shfl_xor_sync(0xffffffffu, l0, 2);
    l1 += __shfl_xor_sync(0xffffffffu, l1, 1);
    l1 += __shfl_xor_sync(0xffffffffu, l1, 2);
    const float inv0 = 1.f / l0;
    const float inv1 = 1.f / l1;

    float* ob = out + (size_t)b * T_ * HS_;
    const int r = i0 + wid * 16 + gid;
    #pragma unroll
    for (int nf = 0; nf < 8; nf++) {
        const int h = nf * 8 + tig * 2;
        float2 v0 = { oacc[nf][0] * inv0, oacc[nf][1] * inv0 };
        float2 v1 = { oacc[nf][2] * inv1, oacc[nf][3] * inv1 };
        *(float2*)(ob + (size_t)r * HS_ + h)       = v0;
        *(float2*)(ob + (size_t)(r + 8) * HS_ + h) = v1;
    }
}

// ===========================================================================
extern "C" void kernel_launch(void* const* d_in, const int* in_sizes, int n_in,
                              void* d_out, int out_size)
{
    const float* x  = (const float*)d_in[0];
    const float* Wq = (const float*)d_in[1];
    const float* Wk = (const float*)d_in[2];
    const float* Wv = (const float*)d_in[3];
    float* out = (float*)d_out;

    static bool configured = false;
    if (!configured) {
        cudaFuncSetAttribute(qkv_h_kernel,
                             cudaFuncAttributeMaxDynamicSharedMemorySize, QKV_SMEM);
        cudaFuncSetAttribute(attn_h2_kernel,
                             cudaFuncAttributeMaxDynamicSharedMemorySize, ATTN_SMEM);
        configured = true;
    }

    wprep_kernel<<<192, 256>>>(Wq, Wk, Wv);
    qkv_h_kernel<<<256, 256, QKV_SMEM>>>(x);
    attn_h2_kernel<<<256, 128, ATTN_SMEM>>>(out);
}